// round 9
// baseline (speedup 1.0000x reference)
#include <cuda_runtime.h>

// Fixed shapes for Latency_78632261255775:
//   x: [8, 3, 224, 224] fp32, T = 100
//   out: [8, 100, 3, 224, 224] fp32
#define N_ELEM   1204224        // 8*3*224*224
#define N4       301056         // N_ELEM/4
#define CHW4     37632          // CHW/4 (float4/uchar4 units per image)
#define BATCH    8
#define T_STEPS  100
#define T_PER    20             // time-steps per fill thread (measured best)
#define MM_BLOCKS 1176          // = N4/256

// Reduction cells live at their identities between runs: statically
// initialized, and reset by fill_kernel block (0,0,0) after each run
// (reset happens after fill's grid-dependency sync, i.e. strictly after
// every spike block has finished reading them).
__device__ unsigned int g_min_bits = 0xFFFFFFFFu;  // monotone-uint domain
__device__ unsigned int g_max_bits = 0u;
__device__ unsigned char g_spikes[N_ELEM];

// Order-preserving float <-> uint mapping (monotone for all finite floats).
__device__ __forceinline__ unsigned int f2u(float f) {
    unsigned int u = __float_as_uint(f);
    return (u & 0x80000000u) ? ~u : (u | 0x80000000u);
}
__device__ __forceinline__ float u2f(unsigned int u) {
    u = (u & 0x80000000u) ? (u & 0x7fffffffu) : ~u;
    return __uint_as_float(u);
}

// Kernel 1: min/max, shortest dependency chain — one float4 per thread,
// block reduce, one fire-and-forget RED.MIN/MAX per block. Each block
// triggers programmatic completion right after its atomics so the spike
// kernel's grid-dependency wait releases at last-atomic time, not at
// kernel-teardown time.
__global__ void __launch_bounds__(256, 8) minmax_kernel(const float* __restrict__ x) {
    __shared__ unsigned int s_min[8], s_max[8];
    int tid = threadIdx.x;
    int gi = blockIdx.x * 256 + tid;          // 0 .. N4-1
    float4 v = ((const float4*)x)[gi];
    unsigned int a = f2u(v.x), b_ = f2u(v.y), c = f2u(v.z), d = f2u(v.w);
    unsigned int lmin = min(min(a, b_), min(c, d));
    unsigned int lmax = max(max(a, b_), max(c, d));
    #pragma unroll
    for (int off = 16; off > 0; off >>= 1) {
        lmin = min(lmin, __shfl_down_sync(0xFFFFFFFFu, lmin, off));
        lmax = max(lmax, __shfl_down_sync(0xFFFFFFFFu, lmax, off));
    }
    int wid = tid >> 5, lid = tid & 31;
    if (lid == 0) { s_min[wid] = lmin; s_max[wid] = lmax; }
    __syncthreads();
    if (tid < 32) {
        lmin = (lid < 8) ? s_min[lid] : 0xFFFFFFFFu;
        lmax = (lid < 8) ? s_max[lid] : 0u;
        #pragma unroll
        for (int off = 4; off > 0; off >>= 1) {
            lmin = min(lmin, __shfl_down_sync(0xFFFFFFFFu, lmin, off));
            lmax = max(lmax, __shfl_down_sync(0xFFFFFFFFu, lmax, off));
        }
        if (lid == 0) {
            atomicMin(&g_min_bits, lmin);     // REDG (result unused)
            atomicMax(&g_max_bits, lmax);
            __threadfence();
            cudaTriggerProgrammaticLaunchCompletion();
        }
    }
}

// Kernel 2 (PDL secondary): per-element spike index as uint8.
// Issues its x load BEFORE the grid-dependency sync (independent of
// kernel 1) so the DRAM latency overlaps the wait.
// FP sequence must match the reference exactly (IEEE ops, no fma/reciprocal):
//   xn = (x - min) / ((max - min) + 1e-8)
//   st = clip(trunc((1 - xn) * 99), 0, 99)
__global__ void __launch_bounds__(256, 8) spike_kernel(const float* __restrict__ x) {
    int i = blockIdx.x * 256 + threadIdx.x;   // 0 .. N4-1
    float4 v = ((const float4*)x)[i];         // independent of minmax results
    cudaGridDependencySynchronize();          // wait for final min/max
    float mn = u2f(g_min_bits);
    float mx = u2f(g_max_bits);
    float denom = __fadd_rn(__fsub_rn(mx, mn), 1e-8f);
    uchar4 st;
    {
        float xn = __fdiv_rn(__fsub_rn(v.x, mn), denom);
        st.x = (unsigned char)max(0, min(99, (int)__fmul_rn(__fsub_rn(1.0f, xn), 99.0f)));
    }
    {
        float xn = __fdiv_rn(__fsub_rn(v.y, mn), denom);
        st.y = (unsigned char)max(0, min(99, (int)__fmul_rn(__fsub_rn(1.0f, xn), 99.0f)));
    }
    {
        float xn = __fdiv_rn(__fsub_rn(v.z, mn), denom);
        st.z = (unsigned char)max(0, min(99, (int)__fmul_rn(__fsub_rn(1.0f, xn), 99.0f)));
    }
    {
        float xn = __fdiv_rn(__fsub_rn(v.w, mn), denom);
        st.w = (unsigned char)max(0, min(99, (int)__fmul_rn(__fsub_rn(1.0f, xn), 99.0f)));
    }
    ((uchar4*)g_spikes)[i] = st;
    __threadfence();
    cudaTriggerProgrammaticLaunchCompletion();
}

// Kernel 3 (PDL secondary): one-hot fill, out[b, t, chw] = (spike == t).
// Each thread owns one uchar4 of spikes and T_PER consecutive t values:
// 1 L2-hit spike load amortized over T_PER coalesced streaming float4 stores.
// Grid-dependency sync BEFORE reading spikes (and before resetting the
// reduction cells — spike blocks may still be reading them under PDL).
__global__ void __launch_bounds__(256, 8) fill_kernel(float* __restrict__ out) {
    cudaGridDependencySynchronize();
    if (blockIdx.x == 0 && blockIdx.y == 0 && blockIdx.z == 0 && threadIdx.x == 0) {
        g_min_bits = 0xFFFFFFFFu;
        g_max_bits = 0u;
    }
    int chw4 = blockIdx.x * 256 + threadIdx.x;  // 0 .. CHW4-1
    int t0 = blockIdx.y * T_PER;
    int b = blockIdx.z;
    uchar4 st = ((const uchar4*)g_spikes)[b * CHW4 + chw4];
    int sx = st.x, sy = st.y, sz = st.z, sw = st.w;
    float4* base = (float4*)out + (size_t)(b * T_STEPS + t0) * CHW4 + chw4;
    #pragma unroll
    for (int k = 0; k < T_PER; k++) {
        int t = t0 + k;
        float4 o;
        o.x = (sx == t) ? 1.0f : 0.0f;
        o.y = (sy == t) ? 1.0f : 0.0f;
        o.z = (sz == t) ? 1.0f : 0.0f;
        o.w = (sw == t) ? 1.0f : 0.0f;
        __stcs(base + (size_t)k * CHW4, o);
    }
}

extern "C" void kernel_launch(void* const* d_in, const int* in_sizes, int n_in,
                              void* d_out, int out_size) {
    const float* x = (const float*)d_in[0];
    float* out = (float*)d_out;

    // Kernel 1: normal launch on stream 0.
    minmax_kernel<<<MM_BLOCKS, 256>>>(x);

    // Kernel 2: PDL secondary — may begin dispatch while kernel 1 runs.
    {
        cudaLaunchConfig_t cfg = {};
        cfg.gridDim = dim3(MM_BLOCKS, 1, 1);
        cfg.blockDim = dim3(256, 1, 1);
        cfg.stream = 0;
        cudaLaunchAttribute attr[1];
        attr[0].id = cudaLaunchAttributeProgrammaticStreamSerialization;
        attr[0].val.programmaticStreamSerializationAllowed = 1;
        cfg.attrs = attr;
        cfg.numAttrs = 1;
        cudaLaunchKernelEx(&cfg, spike_kernel, x);
    }

    // Kernel 3: PDL secondary over spike.
    {
        cudaLaunchConfig_t cfg = {};
        cfg.gridDim = dim3(CHW4 / 256, T_STEPS / T_PER, BATCH);  // (147, 5, 8)
        cfg.blockDim = dim3(256, 1, 1);
        cfg.stream = 0;
        cudaLaunchAttribute attr[1];
        attr[0].id = cudaLaunchAttributeProgrammaticStreamSerialization;
        attr[0].val.programmaticStreamSerializationAllowed = 1;
        cfg.attrs = attr;
        cfg.numAttrs = 1;
        cudaLaunchKernelEx(&cfg, fill_kernel, out);
    }
}

// round 10
// speedup vs baseline: 1.0026x; 1.0026x over previous
#include <cuda_runtime.h>

// Fixed shapes for Latency_78632261255775:
//   x: [8, 3, 224, 224] fp32, T = 100
//   out: [8, 100, 3, 224, 224] fp32
#define N_ELEM   1204224        // 8*3*224*224
#define N4       301056         // N_ELEM/4
#define CHW4     37632          // CHW/4 (float4/uchar4 units per image)
#define BATCH    8
#define T_STEPS  100
#define T_PER    20             // time-steps per fill thread (measured best)
#define MM_BLOCKS 294           // 294 * 256 * 4 = N4 exactly; 2 blocks/SM
#define MM_VPT   4              // float4 loads per minmax thread (MLP)
#define SP_BLOCKS 1176          // = N4/256

// Reduction cells live at their identities between runs: statically
// initialized, and reset by fill_kernel block (0,0,0) after each run
// (fill never reads them and runs strictly after spike_kernel).
__device__ unsigned int g_min_bits = 0xFFFFFFFFu;  // monotone-uint domain
__device__ unsigned int g_max_bits = 0u;
__device__ unsigned char g_spikes[N_ELEM];

// Order-preserving float <-> uint mapping (monotone for all finite floats).
__device__ __forceinline__ unsigned int f2u(float f) {
    unsigned int u = __float_as_uint(f);
    return (u & 0x80000000u) ? ~u : (u | 0x80000000u);
}
__device__ __forceinline__ float u2f(unsigned int u) {
    u = (u & 0x80000000u) ? (u & 0x7fffffffu) : ~u;
    return __uint_as_float(u);
}

// Kernel 1: min/max. MM_VPT independent float4 loads per thread (front-
// batched by ptxas -> MLP ~= MM_VPT, hiding DRAM latency), block reduce,
// one fire-and-forget RED.MIN/MAX per block to the global cells.
__global__ void __launch_bounds__(256, 8) minmax_kernel(const float* __restrict__ x) {
    __shared__ unsigned int s_min[8], s_max[8];
    int tid = threadIdx.x;
    const float4* x4 = (const float4*)x +
                       (size_t)blockIdx.x * 256 * MM_VPT + tid;
    float4 v[MM_VPT];
    #pragma unroll
    for (int j = 0; j < MM_VPT; j++) v[j] = x4[j * 256];   // batched loads
    unsigned int lmin = 0xFFFFFFFFu, lmax = 0u;
    #pragma unroll
    for (int j = 0; j < MM_VPT; j++) {
        unsigned int a = f2u(v[j].x), b_ = f2u(v[j].y),
                     c = f2u(v[j].z), d = f2u(v[j].w);
        lmin = min(lmin, min(min(a, b_), min(c, d)));
        lmax = max(lmax, max(max(a, b_), max(c, d)));
    }
    #pragma unroll
    for (int off = 16; off > 0; off >>= 1) {
        lmin = min(lmin, __shfl_down_sync(0xFFFFFFFFu, lmin, off));
        lmax = max(lmax, __shfl_down_sync(0xFFFFFFFFu, lmax, off));
    }
    int wid = tid >> 5, lid = tid & 31;
    if (lid == 0) { s_min[wid] = lmin; s_max[wid] = lmax; }
    __syncthreads();
    if (tid < 32) {
        lmin = (lid < 8) ? s_min[lid] : 0xFFFFFFFFu;
        lmax = (lid < 8) ? s_max[lid] : 0u;
        #pragma unroll
        for (int off = 4; off > 0; off >>= 1) {
            lmin = min(lmin, __shfl_down_sync(0xFFFFFFFFu, lmin, off));
            lmax = max(lmax, __shfl_down_sync(0xFFFFFFFFu, lmax, off));
        }
        if (lid == 0) {
            atomicMin(&g_min_bits, lmin);     // REDG (result unused)
            atomicMax(&g_max_bits, lmax);
        }
    }
}

// Kernel 2: per-element spike index as uint8.
// FP sequence must match the reference exactly (IEEE ops, no fma/reciprocal):
//   xn = (x - min) / ((max - min) + 1e-8)
//   st = clip(trunc((1 - xn) * 99), 0, 99)
__global__ void __launch_bounds__(256, 8) spike_kernel(const float* __restrict__ x) {
    int i = blockIdx.x * 256 + threadIdx.x;   // 0 .. N4-1
    float mn = u2f(g_min_bits);
    float mx = u2f(g_max_bits);
    float denom = __fadd_rn(__fsub_rn(mx, mn), 1e-8f);
    float4 v = ((const float4*)x)[i];         // L2-hit (read by minmax)
    uchar4 st;
    {
        float xn = __fdiv_rn(__fsub_rn(v.x, mn), denom);
        st.x = (unsigned char)max(0, min(99, (int)__fmul_rn(__fsub_rn(1.0f, xn), 99.0f)));
    }
    {
        float xn = __fdiv_rn(__fsub_rn(v.y, mn), denom);
        st.y = (unsigned char)max(0, min(99, (int)__fmul_rn(__fsub_rn(1.0f, xn), 99.0f)));
    }
    {
        float xn = __fdiv_rn(__fsub_rn(v.z, mn), denom);
        st.z = (unsigned char)max(0, min(99, (int)__fmul_rn(__fsub_rn(1.0f, xn), 99.0f)));
    }
    {
        float xn = __fdiv_rn(__fsub_rn(v.w, mn), denom);
        st.w = (unsigned char)max(0, min(99, (int)__fmul_rn(__fsub_rn(1.0f, xn), 99.0f)));
    }
    ((uchar4*)g_spikes)[i] = st;
}

// Kernel 3: one-hot fill, out[b, t, chw] = (spike[b, chw] == t).
// Each thread owns one uchar4 of spikes and T_PER consecutive t values:
// 1 L2-hit spike load amortized over T_PER coalesced streaming float4 stores.
// Block (0,0,0) thread 0 also resets the reduction cells for the next replay.
__global__ void __launch_bounds__(256, 8) fill_kernel(float* __restrict__ out) {
    if (blockIdx.x == 0 && blockIdx.y == 0 && blockIdx.z == 0 && threadIdx.x == 0) {
        g_min_bits = 0xFFFFFFFFu;
        g_max_bits = 0u;
    }
    int chw4 = blockIdx.x * 256 + threadIdx.x;  // 0 .. CHW4-1
    int t0 = blockIdx.y * T_PER;
    int b = blockIdx.z;
    uchar4 st = ((const uchar4*)g_spikes)[b * CHW4 + chw4];
    int sx = st.x, sy = st.y, sz = st.z, sw = st.w;
    float4* base = (float4*)out + (size_t)(b * T_STEPS + t0) * CHW4 + chw4;
    #pragma unroll
    for (int k = 0; k < T_PER; k++) {
        int t = t0 + k;
        float4 o;
        o.x = (sx == t) ? 1.0f : 0.0f;
        o.y = (sy == t) ? 1.0f : 0.0f;
        o.z = (sz == t) ? 1.0f : 0.0f;
        o.w = (sw == t) ? 1.0f : 0.0f;
        __stcs(base + (size_t)k * CHW4, o);
    }
}

extern "C" void kernel_launch(void* const* d_in, const int* in_sizes, int n_in,
                              void* d_out, int out_size) {
    const float* x = (const float*)d_in[0];
    float* out = (float*)d_out;

    minmax_kernel<<<MM_BLOCKS, 256>>>(x);
    spike_kernel<<<SP_BLOCKS, 256>>>(x);
    dim3 fgrid(CHW4 / 256, T_STEPS / T_PER, BATCH);   // (147, 5, 8)
    fill_kernel<<<fgrid, 256>>>(out);
}

// round 11
// speedup vs baseline: 1.0202x; 1.0176x over previous
#include <cuda_runtime.h>

// Fixed shapes for Latency_78632261255775:
//   x: [8, 3, 224, 224] fp32, T = 100
//   out: [8, 100, 3, 224, 224] fp32
#define N_ELEM   1204224        // 8*3*224*224
#define N4       301056         // N_ELEM/4
#define CHW4     37632          // CHW/4 (float4/uchar4 units per image)
#define BATCH    8
#define T_STEPS  100
#define T_PER    20             // time-steps per fill thread (measured best)
#define MM_BLOCKS 1176          // = N4/256 (R8-best minmax shape)
#define FILL_BLOCKS 5880        // 147 * 5 * 8

// Reduction cells live at their identities between runs: statically
// initialized, and reset by the LAST-exiting fill block (strictly after
// every fill block has read them).
__device__ unsigned int g_min_bits = 0xFFFFFFFFu;  // monotone-uint domain
__device__ unsigned int g_max_bits = 0u;
__device__ unsigned int g_fill_exit = 0;

// Order-preserving float <-> uint mapping (monotone for all finite floats).
__device__ __forceinline__ unsigned int f2u(float f) {
    unsigned int u = __float_as_uint(f);
    return (u & 0x80000000u) ? ~u : (u | 0x80000000u);
}
__device__ __forceinline__ float u2f(unsigned int u) {
    u = (u & 0x80000000u) ? (u & 0x7fffffffu) : ~u;
    return __uint_as_float(u);
}

// Kernel 1: min/max (R8-best shape). One float4 per thread, block reduce,
// one fire-and-forget RED.MIN/MAX per block to the global cells.
__global__ void __launch_bounds__(256, 8) minmax_kernel(const float* __restrict__ x) {
    __shared__ unsigned int s_min[8], s_max[8];
    int tid = threadIdx.x;
    int gi = blockIdx.x * 256 + tid;          // 0 .. N4-1
    float4 v = ((const float4*)x)[gi];
    unsigned int a = f2u(v.x), b_ = f2u(v.y), c = f2u(v.z), d = f2u(v.w);
    unsigned int lmin = min(min(a, b_), min(c, d));
    unsigned int lmax = max(max(a, b_), max(c, d));
    #pragma unroll
    for (int off = 16; off > 0; off >>= 1) {
        lmin = min(lmin, __shfl_down_sync(0xFFFFFFFFu, lmin, off));
        lmax = max(lmax, __shfl_down_sync(0xFFFFFFFFu, lmax, off));
    }
    int wid = tid >> 5, lid = tid & 31;
    if (lid == 0) { s_min[wid] = lmin; s_max[wid] = lmax; }
    __syncthreads();
    if (tid < 32) {
        lmin = (lid < 8) ? s_min[lid] : 0xFFFFFFFFu;
        lmax = (lid < 8) ? s_max[lid] : 0u;
        #pragma unroll
        for (int off = 4; off > 0; off >>= 1) {
            lmin = min(lmin, __shfl_down_sync(0xFFFFFFFFu, lmin, off));
            lmax = max(lmax, __shfl_down_sync(0xFFFFFFFFu, lmax, off));
        }
        if (lid == 0) {
            atomicMin(&g_min_bits, lmin);     // REDG (result unused)
            atomicMax(&g_max_bits, lmax);
        }
    }
}

// Kernel 2: fused spike + one-hot fill.
// Each thread: load its float4 of x (L2-hit — x is L2-resident after
// minmax), compute the 4 spike indices ONCE with the exact reference FP
// sequence (IEEE ops, no fma/reciprocal):
//   xn = (x - min) / ((max - min) + 1e-8)
//   st = clip(trunc((1 - xn) * 99), 0, 99)
// then emit T_PER coalesced streaming float4 stores (proven store engine:
// grid (147, 5, 8), 5 waves). MUFU cost (4 divides/thread, 6.0M total) is
// ~64% of MUFU capacity spread over the store-bound window — hidden.
// The LAST-exiting block resets the reduction cells for the next replay.
__global__ void __launch_bounds__(256, 8) fill_kernel(const float* __restrict__ x,
                                                      float* __restrict__ out) {
    int chw4 = blockIdx.x * 256 + threadIdx.x;  // 0 .. CHW4-1
    int t0 = blockIdx.y * T_PER;
    int b = blockIdx.z;
    float mn = u2f(g_min_bits);
    float mx = u2f(g_max_bits);
    float denom = __fadd_rn(__fsub_rn(mx, mn), 1e-8f);
    float4 v = ((const float4*)x)[b * CHW4 + chw4];   // L2-hit
    int sx, sy, sz, sw;
    {
        float xn = __fdiv_rn(__fsub_rn(v.x, mn), denom);
        sx = max(0, min(99, (int)__fmul_rn(__fsub_rn(1.0f, xn), 99.0f)));
    }
    {
        float xn = __fdiv_rn(__fsub_rn(v.y, mn), denom);
        sy = max(0, min(99, (int)__fmul_rn(__fsub_rn(1.0f, xn), 99.0f)));
    }
    {
        float xn = __fdiv_rn(__fsub_rn(v.z, mn), denom);
        sz = max(0, min(99, (int)__fmul_rn(__fsub_rn(1.0f, xn), 99.0f)));
    }
    {
        float xn = __fdiv_rn(__fsub_rn(v.w, mn), denom);
        sw = max(0, min(99, (int)__fmul_rn(__fsub_rn(1.0f, xn), 99.0f)));
    }
    float4* base = (float4*)out + (size_t)(b * T_STEPS + t0) * CHW4 + chw4;
    #pragma unroll
    for (int k = 0; k < T_PER; k++) {
        int t = t0 + k;
        float4 o;
        o.x = (sx == t) ? 1.0f : 0.0f;
        o.y = (sy == t) ? 1.0f : 0.0f;
        o.z = (sz == t) ? 1.0f : 0.0f;
        o.w = (sw == t) ? 1.0f : 0.0f;
        __stcs(base + (size_t)k * CHW4, o);
    }
    // Replay-safe reset: last block to finish (all blocks have already read
    // g_min_bits/g_max_bits at their start, before their exit increment).
    if (threadIdx.x == 0) {
        __threadfence();
        unsigned int prev = atomicAdd(&g_fill_exit, 1u);
        if (prev == FILL_BLOCKS - 1) {
            g_min_bits = 0xFFFFFFFFu;
            g_max_bits = 0u;
            g_fill_exit = 0;
        }
    }
}

extern "C" void kernel_launch(void* const* d_in, const int* in_sizes, int n_in,
                              void* d_out, int out_size) {
    const float* x = (const float*)d_in[0];
    float* out = (float*)d_out;

    minmax_kernel<<<MM_BLOCKS, 256>>>(x);
    dim3 fgrid(CHW4 / 256, T_STEPS / T_PER, BATCH);   // (147, 5, 8)
    fill_kernel<<<fgrid, 256>>>(x, out);
}